// round 15
// baseline (speedup 1.0000x reference)
#include <cuda_runtime.h>
#include <cuda_fp16.h>
#include <mma.h>
#include <math.h>
#include <cstdint>

using namespace nvcuda;

// Problem constants
static constexpr int NN   = 10000;
static constexpr int EE   = 320000;
static constexpr int EN   = EE + NN;        // edges + self loops
static constexpr int IND  = 512;
static constexpr int HIDD = 128;
static constexpr int OUTD = 128;
static constexpr int HEADS = 4;
static constexpr int GC    = 64;
static constexpr int FEAT  = HEADS * GC;    // 256
static constexpr float NEG_SLOPE = 0.2f;
static constexpr int MAXDEG = 256;

// convert segments (in float4 units)
static constexpr int X4  = NN * IND / 4;
static constexpr int W14 = IND * HIDD / 4;
static constexpr int W24 = HIDD * OUTD / 4;
static constexpr int WG4 = OUTD * FEAT / 4;
static constexpr int CV4 = X4 + W14 + W24 + WG4;

// -------- scratch (device globals: no allocation allowed) --------
__device__ __half d_xh [(size_t)NN * IND];
__device__ __half d_xl [(size_t)NN * IND];
__device__ __half d_w1h[IND * HIDD];
__device__ __half d_w1l[IND * HIDD];
__device__ __half d_w2h[HIDD * OUTD];
__device__ __half d_w2l[HIDD * OUTD];
__device__ __half d_wgh[OUTD * FEAT];
__device__ __half d_wgl[OUTD * FEAT];
__device__ float  d_c32[2 * (size_t)NN * HIDD];   // split-K partials for GEMM1
__device__ __half d_h1h[(size_t)NN * HIDD];
__device__ __half d_h1l[(size_t)NN * HIDD];
__device__ __half d_h2h[(size_t)NN * OUTD];
__device__ __half d_h2l[(size_t)NN * OUTD];
__device__ __half d_g16[(size_t)NN * FEAT];
__device__ float  d_asrc[NN * HEADS];
__device__ float  d_adst[NN * HEADS];
__device__ int    d_cnt[NN];          // zero-init; count fills, fill drains to 0
__device__ int    d_off[NN + 1];
__device__ int    d_src_csr[EN];
__device__ int    d_is64;

// -------- helpers --------
__device__ __forceinline__ void load_edge(const void* ei, int is64, int tid,
                                          int& s, int& d) {
    if (tid < EE) {
        if (is64) {
            const long long* p = (const long long*)ei;
            s = (int)p[tid];
            d = (int)p[EE + tid];
        } else {
            const int* p = (const int*)ei;
            s = p[tid];
            d = p[EE + tid];
        }
    } else {
        s = d = tid - EE;
    }
}

__device__ __forceinline__ void cp16(uint32_t smem_dst, const void* gsrc, bool pred) {
    int sz = pred ? 16 : 0;
    asm volatile("cp.async.ca.shared.global [%0], [%1], 16, %2;\n"
                 :: "r"(smem_dst), "l"(gsrc), "r"(sz));
}
__device__ __forceinline__ void cp_commit() {
    asm volatile("cp.async.commit_group;\n");
}
__device__ __forceinline__ void cp_wait0() {
    asm volatile("cp.async.wait_group 0;\n");
}

// -------- setup: detect int64 vs int32 edge_index --------
__global__ void setup_kernel(const int* ei) {
    if (threadIdx.x == 0) {
        int ok64 = 1;
        for (int i = 1; i < 256; i += 2)
            if (ei[i] != 0) { ok64 = 0; break; }
        d_is64 = ok64;
    }
}

// -------- merged split-convert for x, W1, W2, Wg --------
__global__ void convert_all_kernel(const float* __restrict__ x,
                                   const float* __restrict__ W1,
                                   const float* __restrict__ W2,
                                   const float* __restrict__ Wg) {
    int i = blockIdx.x * blockDim.x + threadIdx.x;
    if (i >= CV4) return;
    const float* src;
    __half *hi, *lo;
    int off;
    if (i < X4)                  { src = x;  hi = d_xh;  lo = d_xl;  off = i; }
    else if (i < X4 + W14)       { src = W1; hi = d_w1h; lo = d_w1l; off = i - X4; }
    else if (i < X4 + W14 + W24) { src = W2; hi = d_w2h; lo = d_w2l; off = i - X4 - W14; }
    else                         { src = Wg; hi = d_wgh; lo = d_wgl; off = i - X4 - W14 - W24; }
    float4 v = ((const float4*)src)[off];
    __half h0 = __float2half_rn(v.x), h1 = __float2half_rn(v.y);
    __half h2 = __float2half_rn(v.z), h3 = __float2half_rn(v.w);
    ((__half2*)hi)[2 * off]     = __halves2half2(h0, h1);
    ((__half2*)hi)[2 * off + 1] = __halves2half2(h2, h3);
    ((__half2*)lo)[2 * off]     = __floats2half2_rn(v.x - __half2float(h0),
                                                    v.y - __half2float(h1));
    ((__half2*)lo)[2 * off + 1] = __floats2half2_rn(v.z - __half2float(h2),
                                                    v.w - __half2float(h3));
}

// -------- CSR build --------
__global__ void count_kernel(const void* __restrict__ ei) {
    int tid = blockIdx.x * blockDim.x + threadIdx.x;
    if (tid >= EN) return;
    int s, d;
    load_edge(ei, d_is64, tid, s, d);
    atomicAdd(&d_cnt[d], 1);
}

// single-block exclusive scan: 1024 threads, 10 elems each (contiguous)
static constexpr int SCH = 10;   // 1024*10 = 10240 >= NN
__global__ void scan_kernel() {
    __shared__ int wsum[32];
    const int t    = threadIdx.x;
    const int lane = t & 31;
    const int wid  = t >> 5;
    const int base = t * SCH;

    int vals[SCH];
    int s = 0;
    #pragma unroll
    for (int i = 0; i < SCH; i++) {
        int idx = base + i;
        int v = (idx < NN) ? d_cnt[idx] : 0;
        vals[i] = s;
        s += v;
    }
    int ws = s;
    #pragma unroll
    for (int o = 1; o < 32; o <<= 1) {
        int u = __shfl_up_sync(0xFFFFFFFFu, ws, o);
        if (lane >= o) ws += u;
    }
    if (lane == 31) wsum[wid] = ws;
    __syncthreads();
    if (wid == 0) {
        int w = (lane < 32) ? wsum[lane] : 0;
        int iw = w;
        #pragma unroll
        for (int o = 1; o < 32; o <<= 1) {
            int u = __shfl_up_sync(0xFFFFFFFFu, iw, o);
            if (lane >= o) iw += u;
        }
        wsum[lane] = iw - w;
    }
    __syncthreads();
    int thr_off = wsum[wid] + ws - s;
    #pragma unroll
    for (int i = 0; i < SCH; i++) {
        int idx = base + i;
        if (idx < NN) d_off[idx] = thr_off + vals[i];
    }
    if (t == 1023) d_off[NN] = wsum[31] + ws;
}

__global__ void fill_kernel(const void* __restrict__ ei) {
    int tid = blockIdx.x * blockDim.x + threadIdx.x;
    if (tid >= EN) return;
    int s, d;
    load_edge(ei, d_is64, tid, s, d);
    int pos = atomicSub(&d_cnt[d], 1) - 1;
    d_src_csr[d_off[d] + pos] = s;
}

// -------- split-fp16 tensor-core GEMM, cp.async 2-stage, term-outer MMA ----
// C = Ah@Bh + Ah@Bl + Al@Bh (fp32 acc). Inputs pre-split fp16 hi/lo.
// Tile: BM=64, BN=64, BK=32. 128 threads = 4 warps (2x2 grid of 32x32 tiles).
// gridDim.z = split-K factor; Of != null -> raw fp32 partial to Of[z-half].
static constexpr int LDA_S = 40;
static constexpr int LDB_S = 72;
static constexpr int LDC_S = 68;
static constexpr int ABUF = 64 * LDA_S;
static constexpr int BBUF = 32 * LDB_S;
static constexpr int STG  = 2 * ABUF + 2 * BBUF;

__global__ void __launch_bounds__(128) gemm_wmma(
        const __half* __restrict__ Ah, const __half* __restrict__ Al,
        const __half* __restrict__ Bh, const __half* __restrict__ Bl,
        const float* __restrict__ bias,
        __half* __restrict__ Oh, __half* __restrict__ Ol,
        float* __restrict__ Of,
        int M, int N, int K, int do_relu) {
    __shared__ __align__(16) __half smh[2 * STG];

    const int t   = threadIdx.x;
    const int wid = t >> 5;
    const int wm  = wid >> 1;
    const int wn  = wid & 1;
    const int m0  = blockIdx.y * 64;
    const int n0  = blockIdx.x * 64;
    const int kspan = K / gridDim.z;
    const int kbase = blockIdx.z * kspan;
    const int nt  = kspan / 32;

    const uint32_t smbase = (uint32_t)__cvta_generic_to_shared(smh);

    auto load_tile = [&](int k0, int stg) {
        const uint32_t sb = smbase + stg * STG * 2;
        #pragma unroll
        for (int i = 0; i < 2; i++) {
            int c = t + i * 128;
            {   // A hi/lo
                int row = c >> 2, col = (c & 3) * 8;
                bool ok = (m0 + row) < M;
                size_t go = (size_t)(m0 + row) * K + k0 + col;
                uint32_t so = sb + (row * LDA_S + col) * 2;
                cp16(so, Ah + go, ok);
                cp16(so + ABUF * 2, Al + go, ok);
            }
            {   // B hi/lo
                int row = c >> 3, col = (c & 7) * 8;
                size_t go = (size_t)(k0 + row) * N + n0 + col;
                uint32_t so = sb + (2 * ABUF + row * LDB_S + col) * 2;
                cp16(so, Bh + go, true);
                cp16(so + BBUF * 2, Bl + go, true);
            }
        }
    };

    load_tile(kbase, 0);
    cp_commit();

    wmma::fragment<wmma::accumulator, 16, 16, 16, float> acc[2][2];
    #pragma unroll
    for (int i = 0; i < 2; i++)
        #pragma unroll
        for (int j = 0; j < 2; j++)
            wmma::fill_fragment(acc[i][j], 0.f);

    cp_wait0();
    __syncthreads();

    for (int tile = 0; tile < nt; tile++) {
        const int cur = tile & 1;
        if (tile + 1 < nt) {
            load_tile(kbase + (tile + 1) * 32, cur ^ 1);
            cp_commit();
        }

        const __half* Ash = smh + cur * STG;
        const __half* Asl = Ash + ABUF;
        const __half* Bsh = smh + cur * STG + 2 * ABUF;
        const __half* Bsl = Bsh + BBUF;

        #pragma unroll
        for (int kk = 0; kk < 32; kk += 16) {
            wmma::fragment<wmma::matrix_a, 16, 16, 16, __half, wmma::row_major> afh[2], afl[2];
            wmma::fragment<wmma::matrix_b, 16, 16, 16, __half, wmma::row_major> bfh[2], bfl[2];
            #pragma unroll
            for (int ni = 0; ni < 2; ni++) {
                wmma::load_matrix_sync(bfh[ni], Bsh + kk * LDB_S + wn * 32 + ni * 16, LDB_S);
                wmma::load_matrix_sync(bfl[ni], Bsl + kk * LDB_S + wn * 32 + ni * 16, LDB_S);
            }
            #pragma unroll
            for (int mi = 0; mi < 2; mi++) {
                const int ro = (wm * 32 + mi * 16) * LDA_S + kk;
                wmma::load_matrix_sync(afh[mi], Ash + ro, LDA_S);
                wmma::load_matrix_sync(afl[mi], Asl + ro, LDA_S);
            }
            #pragma unroll
            for (int mi = 0; mi < 2; mi++)
                #pragma unroll
                for (int ni = 0; ni < 2; ni++)
                    wmma::mma_sync(acc[mi][ni], afh[mi], bfh[ni], acc[mi][ni]);
            #pragma unroll
            for (int mi = 0; mi < 2; mi++)
                #pragma unroll
                for (int ni = 0; ni < 2; ni++)
                    wmma::mma_sync(acc[mi][ni], afh[mi], bfl[ni], acc[mi][ni]);
            #pragma unroll
            for (int mi = 0; mi < 2; mi++)
                #pragma unroll
                for (int ni = 0; ni < 2; ni++)
                    wmma::mma_sync(acc[mi][ni], afl[mi], bfh[ni], acc[mi][ni]);
        }

        if (tile + 1 < nt) cp_wait0();
        __syncthreads();
    }

    float* Cf = (float*)smh;
    #pragma unroll
    for (int mi = 0; mi < 2; mi++)
        #pragma unroll
        for (int ni = 0; ni < 2; ni++)
            wmma::store_matrix_sync(
                &Cf[(wm * 32 + mi * 16) * LDC_S + wn * 32 + ni * 16],
                acc[mi][ni], LDC_S, wmma::mem_row_major);
    __syncthreads();

    {
        const int row = t >> 1;
        const int c0  = (t & 1) * 32;
        if (m0 + row < M) {
            if (Of) {
                // raw fp32 partial for this z-half
                float* op = Of + (size_t)blockIdx.z * M * N
                               + (size_t)(m0 + row) * N + n0 + c0;
                #pragma unroll
                for (int j = 0; j < 32; j += 4)
                    *(float4*)(op + j) = *(float4*)&Cf[row * LDC_S + c0 + j];
            } else {
                #pragma unroll
                for (int j = 0; j < 32; j += 2) {
                    float v0 = Cf[row * LDC_S + c0 + j];
                    float v1 = Cf[row * LDC_S + c0 + j + 1];
                    if (bias) {
                        v0 += bias[n0 + c0 + j];
                        v1 += bias[n0 + c0 + j + 1];
                    }
                    if (do_relu) { v0 = fmaxf(v0, 0.f); v1 = fmaxf(v1, 0.f); }
                    __half h0 = __float2half_rn(v0), h1 = __float2half_rn(v1);
                    size_t o = (size_t)(m0 + row) * N + n0 + c0 + j;
                    *(__half2*)&Oh[o] = __halves2half2(h0, h1);
                    if (Ol)
                        *(__half2*)&Ol[o] = __floats2half2_rn(
                            v0 - __half2float(h0), v1 - __half2float(h1));
                }
            }
        }
    }
}

// -------- finalize GEMM1 split-K: h1 = relu(partA + partB + b1), split ----
__global__ void finalize_h1_kernel(const float* __restrict__ bias) {
    int i = blockIdx.x * blockDim.x + threadIdx.x;   // float4 index
    if (i >= NN * HIDD / 4) return;
    float4 a = ((const float4*)d_c32)[i];
    float4 b = ((const float4*)(d_c32 + (size_t)NN * HIDD))[i];
    int col = (i * 4) & (HIDD - 1);
    float v0 = fmaxf(a.x + b.x + bias[col + 0], 0.f);
    float v1 = fmaxf(a.y + b.y + bias[col + 1], 0.f);
    float v2 = fmaxf(a.z + b.z + bias[col + 2], 0.f);
    float v3 = fmaxf(a.w + b.w + bias[col + 3], 0.f);
    __half h0 = __float2half_rn(v0), h1 = __float2half_rn(v1);
    __half h2 = __float2half_rn(v2), h3 = __float2half_rn(v3);
    ((__half2*)d_h1h)[2 * i]     = __halves2half2(h0, h1);
    ((__half2*)d_h1h)[2 * i + 1] = __halves2half2(h2, h3);
    ((__half2*)d_h1l)[2 * i]     = __floats2half2_rn(v0 - __half2float(h0),
                                                     v1 - __half2float(h1));
    ((__half2*)d_h1l)[2 * i + 1] = __floats2half2_rn(v2 - __half2float(h2),
                                                     v3 - __half2float(h3));
}

// -------- attention coefficients from fp16 g: one warp per (node, head) ----
__global__ void attn_coef_kernel(const float* __restrict__ att_src,
                                 const float* __restrict__ att_dst) {
    int warp = (blockIdx.x * blockDim.x + threadIdx.x) >> 5;
    int lane = threadIdx.x & 31;
    if (warp >= NN * HEADS) return;
    int n = warp / HEADS, h = warp % HEADS;
    const __half2* gp = (const __half2*)(d_g16 + (size_t)n * FEAT + h * GC);
    float2 gv = __half22float2(gp[lane]);
    float ss = gv.x * att_src[h * GC + 2 * lane] +
               gv.y * att_src[h * GC + 2 * lane + 1];
    float sd = gv.x * att_dst[h * GC + 2 * lane] +
               gv.y * att_dst[h * GC + 2 * lane + 1];
    #pragma unroll
    for (int o = 16; o; o >>= 1) {
        ss += __shfl_xor_sync(0xFFFFFFFFu, ss, o);
        sd += __shfl_xor_sync(0xFFFFFFFFu, sd, o);
    }
    if (lane == 0) {
        d_asrc[n * HEADS + h] = ss;
        d_adst[n * HEADS + h] = sd;
    }
}

// -------- gather aggregation: two-pass, fp16 features in pass 2 --------
__global__ void __launch_bounds__(256) gather_kernel(float* __restrict__ out,
                                                     const float* __restrict__ bias_g) {
    __shared__ float s_ex[4][MAXDEG * HEADS];
    __shared__ int   s_src[4][MAXDEG];

    const int grp  = threadIdx.x >> 6;
    const int t    = threadIdx.x & 63;
    const int node = blockIdx.x * 4 + grp;
    const int h    = t >> 4;
    const int l16  = t & 15;

    const int beg = d_off[node];
    const int deg = d_off[node + 1] - beg;
    const int cached = (deg < MAXDEG) ? deg : MAXDEG;

    for (int j = t; j < cached; j += 64)
        s_src[grp][j] = d_src_csr[beg + j];
    __syncthreads();

    const float adst_h = d_adst[node * HEADS + h];

    float psum = 0.f;
    for (int j = l16; j < deg; j += 16) {
        int s = (j < MAXDEG) ? s_src[grp][j] : d_src_csr[beg + j];
        float e = d_asrc[s * HEADS + h] + adst_h;
        e = (e > 0.f) ? e : NEG_SLOPE * e;
        float ex = __expf(e);
        if (j < MAXDEG) s_ex[grp][j * HEADS + h] = ex;
        psum += ex;
    }
    #pragma unroll
    for (int o = 8; o; o >>= 1)
        psum += __shfl_xor_sync(0xFFFFFFFFu, psum, o);
    const float inv = __frcp_rn(psum);
    __syncthreads();

    float4 acc = make_float4(0.f, 0.f, 0.f, 0.f);
    #pragma unroll 8
    for (int j = 0; j < cached; j++) {
        float alpha = s_ex[grp][j * HEADS + h] * inv;
        int s = s_src[grp][j];
        const __half2* gp = (const __half2*)&d_g16[(size_t)s * FEAT + 4 * t];
        float2 f01 = __half22float2(gp[0]);
        float2 f23 = __half22float2(gp[1]);
        acc.x = fmaf(f01.x, alpha, acc.x);
        acc.y = fmaf(f01.y, alpha, acc.y);
        acc.z = fmaf(f23.x, alpha, acc.z);
        acc.w = fmaf(f23.y, alpha, acc.w);
    }
    for (int j = cached; j < deg; j++) {
        int s = d_src_csr[beg + j];
        float e = d_asrc[s * HEADS + h] + adst_h;
        e = (e > 0.f) ? e : NEG_SLOPE * e;
        float alpha = __expf(e) * inv;
        const __half2* gp = (const __half2*)&d_g16[(size_t)s * FEAT + 4 * t];
        float2 f01 = __half22float2(gp[0]);
        float2 f23 = __half22float2(gp[1]);
        acc.x = fmaf(f01.x, alpha, acc.x);
        acc.y = fmaf(f01.y, alpha, acc.y);
        acc.z = fmaf(f23.x, alpha, acc.z);
        acc.w = fmaf(f23.y, alpha, acc.w);
    }

    float4 bv = *(const float4*)&bias_g[4 * t];
    acc.x += bv.x; acc.y += bv.y; acc.z += bv.z; acc.w += bv.w;
    *(float4*)&out[(size_t)node * FEAT + 4 * t] = acc;
}

// ----------------------------------------------------------------------------
extern "C" void kernel_launch(void* const* d_in, const int* in_sizes, int n_in,
                              void* d_out, int out_size) {
    const float* x        = (const float*)d_in[0];
    const void*  ei       = d_in[1];
    const float* W1       = (const float*)d_in[2];
    const float* b1       = (const float*)d_in[3];
    const float* W2       = (const float*)d_in[4];
    const float* b2       = (const float*)d_in[5];
    const float* Wg       = (const float*)d_in[6];
    const float* att_src  = (const float*)d_in[7];
    const float* att_dst  = (const float*)d_in[8];
    const float* bias_g   = (const float*)d_in[9];
    float* out = (float*)d_out;

    void *p_xh, *p_xl, *p_w1h, *p_w1l, *p_w2h, *p_w2l, *p_wgh, *p_wgl;
    void *p_c32, *p_h1h, *p_h1l, *p_h2h, *p_h2l, *p_g16;
    cudaGetSymbolAddress(&p_xh, d_xh);   cudaGetSymbolAddress(&p_xl, d_xl);
    cudaGetSymbolAddress(&p_w1h, d_w1h); cudaGetSymbolAddress(&p_w1l, d_w1l);
    cudaGetSymbolAddress(&p_w2h, d_w2h); cudaGetSymbolAddress(&p_w2l, d_w2l);
    cudaGetSymbolAddress(&p_wgh, d_wgh); cudaGetSymbolAddress(&p_wgl, d_wgl);
    cudaGetSymbolAddress(&p_c32, d_c32);
    cudaGetSymbolAddress(&p_h1h, d_h1h); cudaGetSymbolAddress(&p_h1l, d_h1l);
    cudaGetSymbolAddress(&p_h2h, d_h2h); cudaGetSymbolAddress(&p_h2l, d_h2l);
    cudaGetSymbolAddress(&p_g16, d_g16);

    setup_kernel<<<1, 32>>>((const int*)ei);                             // 0
    convert_all_kernel<<<(CV4 + 255) / 256, 256>>>(x, W1, W2, Wg);       // 1
    count_kernel<<<(EN + 255) / 256, 256>>>(ei);                         // 2
    {   // 3 (profiled): GEMM1 split-K=2, fp32 partials
        dim3 grid(HIDD / 64, (NN + 63) / 64, 2);
        gemm_wmma<<<grid, 128>>>((const __half*)p_xh, (const __half*)p_xl,
                                 (const __half*)p_w1h, (const __half*)p_w1l,
                                 nullptr, nullptr, nullptr, (float*)p_c32,
                                 NN, HIDD, IND, 0);
    }
    scan_kernel<<<1, 1024>>>();                                          // 4
    fill_kernel<<<(EN + 255) / 256, 256>>>(ei);                          // 5
    finalize_h1_kernel<<<(NN * HIDD / 4 + 255) / 256, 256>>>(b1);        // 6
    {   // 7: GEMM2  h2 = h1@W2 + b2
        dim3 grid(OUTD / 64, (NN + 63) / 64, 1);
        gemm_wmma<<<grid, 128>>>((const __half*)p_h1h, (const __half*)p_h1l,
                                 (const __half*)p_w2h, (const __half*)p_w2l,
                                 b2, (__half*)p_h2h, (__half*)p_h2l, nullptr,
                                 NN, OUTD, HIDD, 0);
    }
    {   // 8: GEMM3  g = h2@Wg  (hi only out)
        dim3 grid(FEAT / 64, (NN + 63) / 64, 1);
        gemm_wmma<<<grid, 128>>>((const __half*)p_h2h, (const __half*)p_h2l,
                                 (const __half*)p_wgh, (const __half*)p_wgl,
                                 nullptr, (__half*)p_g16, nullptr, nullptr,
                                 NN, FEAT, OUTD, 0);
    }
    {   // 9
        int warps = NN * HEADS;
        attn_coef_kernel<<<(warps * 32 + 255) / 256, 256>>>(att_src, att_dst);
    }
    gather_kernel<<<NN / 4, 256>>>(out, bias_g);                         // 10
}

// round 16
// speedup vs baseline: 1.0099x; 1.0099x over previous
#include <cuda_runtime.h>
#include <cuda_fp16.h>
#include <mma.h>
#include <math.h>
#include <cstdint>

using namespace nvcuda;

// Problem constants
static constexpr int NN   = 10000;
static constexpr int EE   = 320000;
static constexpr int EN   = EE + NN;        // edges + self loops
static constexpr int IND  = 512;
static constexpr int HIDD = 128;
static constexpr int OUTD = 128;
static constexpr int HEADS = 4;
static constexpr int GC    = 64;
static constexpr int FEAT  = HEADS * GC;    // 256
static constexpr float NEG_SLOPE = 0.2f;
static constexpr int MAXDEG = 256;

// convert segments (in float4 units)
static constexpr int X4  = NN * IND / 4;
static constexpr int W14 = IND * HIDD / 4;
static constexpr int W24 = HIDD * OUTD / 4;
static constexpr int WG4 = OUTD * FEAT / 4;
static constexpr int CV4 = X4 + W14 + W24 + WG4;

// -------- scratch (device globals: no allocation allowed) --------
__device__ __half d_xh [(size_t)NN * IND];
__device__ __half d_xl [(size_t)NN * IND];
__device__ __half d_w1h[IND * HIDD];
__device__ __half d_w1l[IND * HIDD];
__device__ __half d_w2h[HIDD * OUTD];
__device__ __half d_w2l[HIDD * OUTD];
__device__ __half d_wgh[OUTD * FEAT];
__device__ __half d_wgl[OUTD * FEAT];
__device__ __half d_h1h[(size_t)NN * HIDD];
__device__ __half d_h1l[(size_t)NN * HIDD];
__device__ __half d_h2h[(size_t)NN * OUTD];
__device__ __half d_h2l[(size_t)NN * OUTD];
__device__ __half d_g16[(size_t)NN * FEAT];
__device__ float  d_asrc[NN * HEADS];
__device__ float  d_adst[NN * HEADS];
__device__ int    d_cnt[NN];          // zero-init; count fills, fill drains to 0
__device__ int    d_off[NN + 1];
__device__ int    d_src_csr[EN];
__device__ int    d_is64;

// -------- helpers --------
__device__ __forceinline__ void load_edge(const void* ei, int is64, int tid,
                                          int& s, int& d) {
    if (tid < EE) {
        if (is64) {
            const long long* p = (const long long*)ei;
            s = (int)p[tid];
            d = (int)p[EE + tid];
        } else {
            const int* p = (const int*)ei;
            s = p[tid];
            d = p[EE + tid];
        }
    } else {
        s = d = tid - EE;
    }
}

__device__ __forceinline__ void cp16(uint32_t smem_dst, const void* gsrc, bool pred) {
    int sz = pred ? 16 : 0;
    asm volatile("cp.async.ca.shared.global [%0], [%1], 16, %2;\n"
                 :: "r"(smem_dst), "l"(gsrc), "r"(sz));
}
__device__ __forceinline__ void cp_commit() {
    asm volatile("cp.async.commit_group;\n");
}
__device__ __forceinline__ void cp_wait0() {
    asm volatile("cp.async.wait_group 0;\n");
}

// -------- merged split-convert for x, W1, W2, Wg  (+ edge dtype detect) ----
__global__ void convert_all_kernel(const float* __restrict__ x,
                                   const float* __restrict__ W1,
                                   const float* __restrict__ W2,
                                   const float* __restrict__ Wg,
                                   const int* __restrict__ ei) {
    int i = blockIdx.x * blockDim.x + threadIdx.x;
    if (i == 0) {   // edge dtype detect: int64 node ids < 10000 -> odd words 0
        int ok64 = 1;
        for (int k = 1; k < 256; k += 2)
            if (ei[k] != 0) { ok64 = 0; break; }
        d_is64 = ok64;
    }
    if (i >= CV4) return;
    const float* src;
    __half *hi, *lo;
    int off;
    if (i < X4)                  { src = x;  hi = d_xh;  lo = d_xl;  off = i; }
    else if (i < X4 + W14)       { src = W1; hi = d_w1h; lo = d_w1l; off = i - X4; }
    else if (i < X4 + W14 + W24) { src = W2; hi = d_w2h; lo = d_w2l; off = i - X4 - W14; }
    else                         { src = Wg; hi = d_wgh; lo = d_wgl; off = i - X4 - W14 - W24; }
    float4 v = ((const float4*)src)[off];
    __half h0 = __float2half_rn(v.x), h1 = __float2half_rn(v.y);
    __half h2 = __float2half_rn(v.z), h3 = __float2half_rn(v.w);
    ((__half2*)hi)[2 * off]     = __halves2half2(h0, h1);
    ((__half2*)hi)[2 * off + 1] = __halves2half2(h2, h3);
    ((__half2*)lo)[2 * off]     = __floats2half2_rn(v.x - __half2float(h0),
                                                    v.y - __half2float(h1));
    ((__half2*)lo)[2 * off + 1] = __floats2half2_rn(v.z - __half2float(h2),
                                                    v.w - __half2float(h3));
}

// -------- CSR build --------
__global__ void count_kernel(const void* __restrict__ ei) {
    int tid = blockIdx.x * blockDim.x + threadIdx.x;
    if (tid >= EN) return;
    int s, d;
    load_edge(ei, d_is64, tid, s, d);
    atomicAdd(&d_cnt[d], 1);
}

// single-block exclusive scan: 1024 threads, 10 elems each (contiguous)
static constexpr int SCH = 10;   // 1024*10 = 10240 >= NN
__global__ void scan_kernel() {
    __shared__ int wsum[32];
    const int t    = threadIdx.x;
    const int lane = t & 31;
    const int wid  = t >> 5;
    const int base = t * SCH;

    int vals[SCH];
    int s = 0;
    #pragma unroll
    for (int i = 0; i < SCH; i++) {
        int idx = base + i;
        int v = (idx < NN) ? d_cnt[idx] : 0;
        vals[i] = s;
        s += v;
    }
    int ws = s;
    #pragma unroll
    for (int o = 1; o < 32; o <<= 1) {
        int u = __shfl_up_sync(0xFFFFFFFFu, ws, o);
        if (lane >= o) ws += u;
    }
    if (lane == 31) wsum[wid] = ws;
    __syncthreads();
    if (wid == 0) {
        int w = (lane < 32) ? wsum[lane] : 0;
        int iw = w;
        #pragma unroll
        for (int o = 1; o < 32; o <<= 1) {
            int u = __shfl_up_sync(0xFFFFFFFFu, iw, o);
            if (lane >= o) iw += u;
        }
        wsum[lane] = iw - w;
    }
    __syncthreads();
    int thr_off = wsum[wid] + ws - s;
    #pragma unroll
    for (int i = 0; i < SCH; i++) {
        int idx = base + i;
        if (idx < NN) d_off[idx] = thr_off + vals[i];
    }
    if (t == 1023) d_off[NN] = wsum[31] + ws;
}

__global__ void fill_kernel(const void* __restrict__ ei) {
    int tid = blockIdx.x * blockDim.x + threadIdx.x;
    if (tid >= EN) return;
    int s, d;
    load_edge(ei, d_is64, tid, s, d);
    int pos = atomicSub(&d_cnt[d], 1) - 1;
    d_src_csr[d_off[d] + pos] = s;
}

// -------- split-fp16 tensor-core GEMM, cp.async 2-stage, term-outer MMA ----
// C = Ah@Bh + Ah@Bl + Al@Bh (fp32 acc). Inputs pre-split fp16 hi/lo.
// Tile: BM=64, BN=64, BK=32. 128 threads = 4 warps (2x2 grid of 32x32 tiles).
// attS/attD non-null (GEMM3): CTA's 64 cols = one head; fuse attention dots.
static constexpr int LDA_S = 40;
static constexpr int LDB_S = 72;
static constexpr int LDC_S = 68;
static constexpr int ABUF = 64 * LDA_S;
static constexpr int BBUF = 32 * LDB_S;
static constexpr int STG  = 2 * ABUF + 2 * BBUF;

__global__ void __launch_bounds__(128) gemm_wmma(
        const __half* __restrict__ Ah, const __half* __restrict__ Al,
        const __half* __restrict__ Bh, const __half* __restrict__ Bl,
        const float* __restrict__ bias,
        __half* __restrict__ Oh, __half* __restrict__ Ol,
        const float* __restrict__ attS, const float* __restrict__ attD,
        int M, int N, int K, int do_relu) {
    __shared__ __align__(16) __half smh[2 * STG];

    const int t   = threadIdx.x;
    const int wid = t >> 5;
    const int wm  = wid >> 1;
    const int wn  = wid & 1;
    const int m0  = blockIdx.y * 64;
    const int n0  = blockIdx.x * 64;
    const int nt  = K / 32;

    const uint32_t smbase = (uint32_t)__cvta_generic_to_shared(smh);

    auto load_tile = [&](int k0, int stg) {
        const uint32_t sb = smbase + stg * STG * 2;
        #pragma unroll
        for (int i = 0; i < 2; i++) {
            int c = t + i * 128;
            {   // A hi/lo
                int row = c >> 2, col = (c & 3) * 8;
                bool ok = (m0 + row) < M;
                size_t go = (size_t)(m0 + row) * K + k0 + col;
                uint32_t so = sb + (row * LDA_S + col) * 2;
                cp16(so, Ah + go, ok);
                cp16(so + ABUF * 2, Al + go, ok);
            }
            {   // B hi/lo
                int row = c >> 3, col = (c & 7) * 8;
                size_t go = (size_t)(k0 + row) * N + n0 + col;
                uint32_t so = sb + (2 * ABUF + row * LDB_S + col) * 2;
                cp16(so, Bh + go, true);
                cp16(so + BBUF * 2, Bl + go, true);
            }
        }
    };

    load_tile(0, 0);
    cp_commit();

    wmma::fragment<wmma::accumulator, 16, 16, 16, float> acc[2][2];
    #pragma unroll
    for (int i = 0; i < 2; i++)
        #pragma unroll
        for (int j = 0; j < 2; j++)
            wmma::fill_fragment(acc[i][j], 0.f);

    cp_wait0();
    __syncthreads();

    for (int tile = 0; tile < nt; tile++) {
        const int cur = tile & 1;
        if (tile + 1 < nt) {
            load_tile((tile + 1) * 32, cur ^ 1);
            cp_commit();
        }

        const __half* Ash = smh + cur * STG;
        const __half* Asl = Ash + ABUF;
        const __half* Bsh = smh + cur * STG + 2 * ABUF;
        const __half* Bsl = Bsh + BBUF;

        #pragma unroll
        for (int kk = 0; kk < 32; kk += 16) {
            wmma::fragment<wmma::matrix_a, 16, 16, 16, __half, wmma::row_major> afh[2], afl[2];
            wmma::fragment<wmma::matrix_b, 16, 16, 16, __half, wmma::row_major> bfh[2], bfl[2];
            #pragma unroll
            for (int ni = 0; ni < 2; ni++) {
                wmma::load_matrix_sync(bfh[ni], Bsh + kk * LDB_S + wn * 32 + ni * 16, LDB_S);
                wmma::load_matrix_sync(bfl[ni], Bsl + kk * LDB_S + wn * 32 + ni * 16, LDB_S);
            }
            #pragma unroll
            for (int mi = 0; mi < 2; mi++) {
                const int ro = (wm * 32 + mi * 16) * LDA_S + kk;
                wmma::load_matrix_sync(afh[mi], Ash + ro, LDA_S);
                wmma::load_matrix_sync(afl[mi], Asl + ro, LDA_S);
            }
            #pragma unroll
            for (int mi = 0; mi < 2; mi++)
                #pragma unroll
                for (int ni = 0; ni < 2; ni++)
                    wmma::mma_sync(acc[mi][ni], afh[mi], bfh[ni], acc[mi][ni]);
            #pragma unroll
            for (int mi = 0; mi < 2; mi++)
                #pragma unroll
                for (int ni = 0; ni < 2; ni++)
                    wmma::mma_sync(acc[mi][ni], afh[mi], bfl[ni], acc[mi][ni]);
            #pragma unroll
            for (int mi = 0; mi < 2; mi++)
                #pragma unroll
                for (int ni = 0; ni < 2; ni++)
                    wmma::mma_sync(acc[mi][ni], afl[mi], bfh[ni], acc[mi][ni]);
        }

        if (tile + 1 < nt) cp_wait0();
        __syncthreads();
    }

    float* Cf = (float*)smh;
    #pragma unroll
    for (int mi = 0; mi < 2; mi++)
        #pragma unroll
        for (int ni = 0; ni < 2; ni++)
            wmma::store_matrix_sync(
                &Cf[(wm * 32 + mi * 16) * LDC_S + wn * 32 + ni * 16],
                acc[mi][ni], LDC_S, wmma::mem_row_major);
    __syncthreads();

    const int row = t >> 1;
    const int c0  = (t & 1) * 32;

    // fused attention coefficients (GEMM3): this CTA's 64 cols = head n0/64
    if (attS) {
        const int h = n0 >> 6;    // GC = 64
        float ps = 0.f, pd = 0.f;
        #pragma unroll
        for (int j = 0; j < 32; j++) {
            float v = Cf[row * LDC_S + c0 + j];     // smem; OOB rows give junk,
            ps += v * attS[h * GC + c0 + j];        // discarded by write guard
            pd += v * attD[h * GC + c0 + j];
        }
        ps += __shfl_xor_sync(0xFFFFFFFFu, ps, 1);  // pair (t, t^1) = same row
        pd += __shfl_xor_sync(0xFFFFFFFFu, pd, 1);
        if ((t & 1) == 0 && (m0 + row) < M) {
            d_asrc[(m0 + row) * HEADS + h] = ps;
            d_adst[(m0 + row) * HEADS + h] = pd;
        }
    }

    if (m0 + row < M) {
        #pragma unroll
        for (int j = 0; j < 32; j += 2) {
            float v0 = Cf[row * LDC_S + c0 + j];
            float v1 = Cf[row * LDC_S + c0 + j + 1];
            if (bias) {
                v0 += bias[n0 + c0 + j];
                v1 += bias[n0 + c0 + j + 1];
            }
            if (do_relu) { v0 = fmaxf(v0, 0.f); v1 = fmaxf(v1, 0.f); }
            __half h0 = __float2half_rn(v0), h1 = __float2half_rn(v1);
            size_t o = (size_t)(m0 + row) * N + n0 + c0 + j;
            *(__half2*)&Oh[o] = __halves2half2(h0, h1);
            if (Ol)
                *(__half2*)&Ol[o] = __floats2half2_rn(
                    v0 - __half2float(h0), v1 - __half2float(h1));
        }
    }
}

// -------- gather aggregation: two-pass, fp16 features in pass 2 --------
__global__ void __launch_bounds__(256) gather_kernel(float* __restrict__ out,
                                                     const float* __restrict__ bias_g) {
    __shared__ float s_ex[4][MAXDEG * HEADS];
    __shared__ int   s_src[4][MAXDEG];

    const int grp  = threadIdx.x >> 6;
    const int t    = threadIdx.x & 63;
    const int node = blockIdx.x * 4 + grp;
    const int h    = t >> 4;
    const int l16  = t & 15;

    const int beg = d_off[node];
    const int deg = d_off[node + 1] - beg;
    const int cached = (deg < MAXDEG) ? deg : MAXDEG;

    for (int j = t; j < cached; j += 64)
        s_src[grp][j] = d_src_csr[beg + j];
    __syncthreads();

    const float adst_h = d_adst[node * HEADS + h];

    float psum = 0.f;
    for (int j = l16; j < deg; j += 16) {
        int s = (j < MAXDEG) ? s_src[grp][j] : d_src_csr[beg + j];
        float e = d_asrc[s * HEADS + h] + adst_h;
        e = (e > 0.f) ? e : NEG_SLOPE * e;
        float ex = __expf(e);
        if (j < MAXDEG) s_ex[grp][j * HEADS + h] = ex;
        psum += ex;
    }
    #pragma unroll
    for (int o = 8; o; o >>= 1)
        psum += __shfl_xor_sync(0xFFFFFFFFu, psum, o);
    const float inv = __frcp_rn(psum);
    __syncthreads();

    float4 acc = make_float4(0.f, 0.f, 0.f, 0.f);
    #pragma unroll 8
    for (int j = 0; j < cached; j++) {
        float alpha = s_ex[grp][j * HEADS + h] * inv;
        int s = s_src[grp][j];
        const __half2* gp = (const __half2*)&d_g16[(size_t)s * FEAT + 4 * t];
        float2 f01 = __half22float2(gp[0]);
        float2 f23 = __half22float2(gp[1]);
        acc.x = fmaf(f01.x, alpha, acc.x);
        acc.y = fmaf(f01.y, alpha, acc.y);
        acc.z = fmaf(f23.x, alpha, acc.z);
        acc.w = fmaf(f23.y, alpha, acc.w);
    }
    for (int j = cached; j < deg; j++) {
        int s = d_src_csr[beg + j];
        float e = d_asrc[s * HEADS + h] + adst_h;
        e = (e > 0.f) ? e : NEG_SLOPE * e;
        float alpha = __expf(e) * inv;
        const __half2* gp = (const __half2*)&d_g16[(size_t)s * FEAT + 4 * t];
        float2 f01 = __half22float2(gp[0]);
        float2 f23 = __half22float2(gp[1]);
        acc.x = fmaf(f01.x, alpha, acc.x);
        acc.y = fmaf(f01.y, alpha, acc.y);
        acc.z = fmaf(f23.x, alpha, acc.z);
        acc.w = fmaf(f23.y, alpha, acc.w);
    }

    float4 bv = *(const float4*)&bias_g[4 * t];
    acc.x += bv.x; acc.y += bv.y; acc.z += bv.z; acc.w += bv.w;
    *(float4*)&out[(size_t)node * FEAT + 4 * t] = acc;
}

// ----------------------------------------------------------------------------
extern "C" void kernel_launch(void* const* d_in, const int* in_sizes, int n_in,
                              void* d_out, int out_size) {
    const float* x        = (const float*)d_in[0];
    const void*  ei       = d_in[1];
    const float* W1       = (const float*)d_in[2];
    const float* b1       = (const float*)d_in[3];
    const float* W2       = (const float*)d_in[4];
    const float* b2       = (const float*)d_in[5];
    const float* Wg       = (const float*)d_in[6];
    const float* att_src  = (const float*)d_in[7];
    const float* att_dst  = (const float*)d_in[8];
    const float* bias_g   = (const float*)d_in[9];
    float* out = (float*)d_out;

    void *p_xh, *p_xl, *p_w1h, *p_w1l, *p_w2h, *p_w2l, *p_wgh, *p_wgl;
    void *p_h1h, *p_h1l, *p_h2h, *p_h2l, *p_g16;
    cudaGetSymbolAddress(&p_xh, d_xh);   cudaGetSymbolAddress(&p_xl, d_xl);
    cudaGetSymbolAddress(&p_w1h, d_w1h); cudaGetSymbolAddress(&p_w1l, d_w1l);
    cudaGetSymbolAddress(&p_w2h, d_w2h); cudaGetSymbolAddress(&p_w2l, d_w2l);
    cudaGetSymbolAddress(&p_wgh, d_wgh); cudaGetSymbolAddress(&p_wgl, d_wgl);
    cudaGetSymbolAddress(&p_h1h, d_h1h); cudaGetSymbolAddress(&p_h1l, d_h1l);
    cudaGetSymbolAddress(&p_h2h, d_h2h); cudaGetSymbolAddress(&p_h2l, d_h2l);
    cudaGetSymbolAddress(&p_g16, d_g16);

    convert_all_kernel<<<(CV4 + 255) / 256, 256>>>(x, W1, W2, Wg,
                                                   (const int*)ei);      // 0
    count_kernel<<<(EN + 255) / 256, 256>>>(ei);                         // 1
    scan_kernel<<<1, 1024>>>();                                          // 2
    {   // 3 (profiled): GEMM1  h1 = relu(x@W1 + b1)
        dim3 grid(HIDD / 64, (NN + 63) / 64);
        gemm_wmma<<<grid, 128>>>((const __half*)p_xh, (const __half*)p_xl,
                                 (const __half*)p_w1h, (const __half*)p_w1l,
                                 b1, (__half*)p_h1h, (__half*)p_h1l,
                                 nullptr, nullptr,
                                 NN, HIDD, IND, 1);
    }
    fill_kernel<<<(EN + 255) / 256, 256>>>(ei);                          // 4
    {   // 5: GEMM2  h2 = h1@W2 + b2
        dim3 grid(OUTD / 64, (NN + 63) / 64);
        gemm_wmma<<<grid, 128>>>((const __half*)p_h1h, (const __half*)p_h1l,
                                 (const __half*)p_w2h, (const __half*)p_w2l,
                                 b2, (__half*)p_h2h, (__half*)p_h2l,
                                 nullptr, nullptr,
                                 NN, OUTD, HIDD, 0);
    }
    {   // 6: GEMM3  g = h2@Wg  (hi out) + fused attention coefficients
        dim3 grid(FEAT / 64, (NN + 63) / 64);
        gemm_wmma<<<grid, 128>>>((const __half*)p_h2h, (const __half*)p_h2l,
                                 (const __half*)p_wgh, (const __half*)p_wgl,
                                 nullptr, (__half*)p_g16, nullptr,
                                 att_src, att_dst,
                                 NN, FEAT, OUTD, 0);
    }
    gather_kernel<<<NN / 4, 256>>>(out, bias_g);                         // 7
}